// round 1
// baseline (speedup 1.0000x reference)
#include <cuda_runtime.h>

#define NN  50000
#define EUN 200000
#define EDN 400000
#define DD  128

// ---------------- scratch (device globals; no allocation) ----------------
__device__ __align__(16) float g_hc[EDN * DD];
__device__ __align__(16) float g_hg[EDN * DD];
__device__ __align__(16) float g_nl[EDN * DD];
__device__ __align__(16) float g_nodeagg[NN * DD];
__device__ __align__(16) float g_esum[EUN * DD];
__device__ __align__(16) float g_cnt[EUN];

__device__ __forceinline__ float sigmoidf_(float x) {
    return __fdividef(1.0f, 1.0f + __expf(-x));
}
__device__ __forceinline__ float siluf_(float x) {
    return x * sigmoidf_(x);
}

// ---------------- zero scratch accumulators ----------------
__global__ void k_zero() {
    size_t stride = (size_t)gridDim.x * blockDim.x;
    size_t i = (size_t)blockIdx.x * blockDim.x + threadIdx.x;
    float4 z = make_float4(0.f, 0.f, 0.f, 0.f);
    for (size_t p = i; p < (size_t)NN * DD / 4; p += stride)  ((float4*)g_nodeagg)[p] = z;
    for (size_t p = i; p < (size_t)EUN * DD / 4; p += stride) ((float4*)g_esum)[p] = z;
    for (size_t p = i; p < (size_t)EUN / 4; p += stride)      ((float4*)g_cnt)[p] = z;
}

// ---------------- kernel 1: gather-fused GEMM  h = silu(concat(ef,tgt,src) @ W1)
// grid.x = EDN/128 row tiles, grid.y = {0: Wc1->g_hc, 1: Wg1->g_hg}
__global__ __launch_bounds__(256) void k_gemm1(
    const float* __restrict__ node_feat, const float* __restrict__ edge_feat,
    const int* __restrict__ src_i, const int* __restrict__ tgt_i, const int* __restrict__ d2u,
    const float* __restrict__ Wc1, const float* __restrict__ Wg1)
{
    __shared__ __align__(16) float As[16][128];
    __shared__ __align__(16) float Bs[16][128];
    __shared__ int idxE[128], idxT[128], idxS[128];

    const int tid = threadIdx.x;
    const int eBase = blockIdx.x * 128;
    const float* __restrict__ W = (blockIdx.y == 0) ? Wc1 : Wg1;
    float* Out = (blockIdx.y == 0) ? g_hc : g_hg;

    if (tid < 128) {
        idxE[tid] = d2u[eBase + tid];
        idxS[tid] = src_i[eBase + tid];
    } else {
        int t = tid - 128;
        idxT[t] = tgt_i[eBase + t];
    }

    const int tm = tid >> 4, tn = tid & 15;
    float acc[8][8];
#pragma unroll
    for (int i = 0; i < 8; i++)
#pragma unroll
        for (int j = 0; j < 8; j++) acc[i][j] = 0.f;

    __syncthreads();

    for (int k0 = 0; k0 < 384; k0 += 16) {
#pragma unroll
        for (int l = 0; l < 2; l++) {
            int flat = tid + l * 256;
            int m = flat >> 2;
            int kq = (flat & 3) << 2;
            const float* p;
            if (k0 < 128)      p = edge_feat + ((size_t)idxE[m] << 7) + (k0 + kq);
            else if (k0 < 256) p = node_feat + ((size_t)idxT[m] << 7) + (k0 - 128 + kq);
            else               p = node_feat + ((size_t)idxS[m] << 7) + (k0 - 256 + kq);
            float4 v = *(const float4*)p;
            As[kq + 0][m] = v.x; As[kq + 1][m] = v.y;
            As[kq + 2][m] = v.z; As[kq + 3][m] = v.w;
        }
#pragma unroll
        for (int l = 0; l < 2; l++) {
            int flat = tid + l * 256;
            int kr = flat >> 5;
            int n = (flat & 31) << 2;
            *(float4*)&Bs[kr][n] = *(const float4*)(W + (size_t)(k0 + kr) * 128 + n);
        }
        __syncthreads();
#pragma unroll
        for (int kk = 0; kk < 16; kk++) {
            float a[8], b[8];
            *(float4*)&a[0] = *(const float4*)&As[kk][tm * 8];
            *(float4*)&a[4] = *(const float4*)&As[kk][tm * 8 + 4];
            *(float4*)&b[0] = *(const float4*)&Bs[kk][tn * 8];
            *(float4*)&b[4] = *(const float4*)&Bs[kk][tn * 8 + 4];
#pragma unroll
            for (int i = 0; i < 8; i++)
#pragma unroll
                for (int j = 0; j < 8; j++) acc[i][j] = fmaf(a[i], b[j], acc[i][j]);
        }
        __syncthreads();
    }

#pragma unroll
    for (int i = 0; i < 8; i++) {
        float* op = Out + ((size_t)(eBase + tm * 8 + i) << 7) + tn * 8;
        float4 v0, v1;
        v0.x = siluf_(acc[i][0]); v0.y = siluf_(acc[i][1]);
        v0.z = siluf_(acc[i][2]); v0.w = siluf_(acc[i][3]);
        v1.x = siluf_(acc[i][4]); v1.y = siluf_(acc[i][5]);
        v1.z = siluf_(acc[i][6]); v1.w = siluf_(acc[i][7]);
        *(float4*)op = v0;
        *(float4*)(op + 4) = v1;
    }
}

// ---------------- kernel 2: y=h@W2, LayerNorm, silu*sigmoid, envelope, node atomics
// 64 rows per block, full 128 cols (LN needs whole row)
__global__ __launch_bounds__(256) void k_gemm2_ln(
    const float* __restrict__ Wc2, const float* __restrict__ Wg2,
    const float* __restrict__ lncg, const float* __restrict__ lncb,
    const float* __restrict__ lngg, const float* __restrict__ lngb,
    const float* __restrict__ smooth_weight, const float* __restrict__ W_env,
    const int* __restrict__ d2u, const int* __restrict__ tgt_i)
{
    __shared__ __align__(16) float Ac[16][64];
    __shared__ __align__(16) float Ag[16][64];
    __shared__ __align__(16) float Bc[16][128];
    __shared__ __align__(16) float Bg[16][128];
    __shared__ float Wenv_s[7][128];
    __shared__ float sw7[64][8];
    __shared__ int idxT[64];

    const int tid = threadIdx.x;
    const int eBase = blockIdx.x * 64;
    const int tm = tid >> 4, tn = tid & 15;

    if (tid < 64) idxT[tid] = tgt_i[eBase + tid];
    for (int f = tid; f < 448; f += 256) {
        int m = f / 7, j = f % 7;
        int u = d2u[eBase + m];
        sw7[m][j] = smooth_weight[(size_t)u * 7 + j];
    }
    for (int f = tid; f < 896; f += 256) Wenv_s[f >> 7][f & 127] = W_env[f];

    float accc[4][8], accg[4][8];
#pragma unroll
    for (int r = 0; r < 4; r++)
#pragma unroll
        for (int j = 0; j < 8; j++) { accc[r][j] = 0.f; accg[r][j] = 0.f; }

    __syncthreads();

    for (int k0 = 0; k0 < 128; k0 += 16) {
        {
            int m = tid >> 2;
            int kq = (tid & 3) << 2;
            float4 v = *(const float4*)(g_hc + ((size_t)(eBase + m) << 7) + k0 + kq);
            Ac[kq + 0][m] = v.x; Ac[kq + 1][m] = v.y; Ac[kq + 2][m] = v.z; Ac[kq + 3][m] = v.w;
            float4 w = *(const float4*)(g_hg + ((size_t)(eBase + m) << 7) + k0 + kq);
            Ag[kq + 0][m] = w.x; Ag[kq + 1][m] = w.y; Ag[kq + 2][m] = w.z; Ag[kq + 3][m] = w.w;
        }
#pragma unroll
        for (int l = 0; l < 2; l++) {
            int flat = tid + l * 256;
            int kr = flat >> 5;
            int n = (flat & 31) << 2;
            *(float4*)&Bc[kr][n] = *(const float4*)(Wc2 + (size_t)(k0 + kr) * 128 + n);
            *(float4*)&Bg[kr][n] = *(const float4*)(Wg2 + (size_t)(k0 + kr) * 128 + n);
        }
        __syncthreads();
#pragma unroll
        for (int kk = 0; kk < 16; kk++) {
            float4 a4 = *(const float4*)&Ac[kk][tm * 4];
            float4 g4 = *(const float4*)&Ag[kk][tm * 4];
            float ac[4] = {a4.x, a4.y, a4.z, a4.w};
            float ag[4] = {g4.x, g4.y, g4.z, g4.w};
            float bc[8], bg[8];
            *(float4*)&bc[0] = *(const float4*)&Bc[kk][tn * 8];
            *(float4*)&bc[4] = *(const float4*)&Bc[kk][tn * 8 + 4];
            *(float4*)&bg[0] = *(const float4*)&Bg[kk][tn * 8];
            *(float4*)&bg[4] = *(const float4*)&Bg[kk][tn * 8 + 4];
#pragma unroll
            for (int r = 0; r < 4; r++)
#pragma unroll
                for (int j = 0; j < 8; j++) {
                    accc[r][j] = fmaf(ac[r], bc[j], accc[r][j]);
                    accg[r][j] = fmaf(ag[r], bg[j], accg[r][j]);
                }
        }
        __syncthreads();
    }

    // epilogue: LN per row (16 threads per row -> width-16 shuffle reduce)
#pragma unroll
    for (int r = 0; r < 4; r++) {
        int row = tm * 4 + r;
        int e = eBase + row;
        float sc = 0.f, sc2 = 0.f, sg = 0.f, sg2 = 0.f;
#pragma unroll
        for (int j = 0; j < 8; j++) {
            sc += accc[r][j]; sc2 += accc[r][j] * accc[r][j];
            sg += accg[r][j]; sg2 += accg[r][j] * accg[r][j];
        }
#pragma unroll
        for (int off = 8; off > 0; off >>= 1) {
            sc  += __shfl_xor_sync(0xffffffffu, sc,  off, 16);
            sc2 += __shfl_xor_sync(0xffffffffu, sc2, off, 16);
            sg  += __shfl_xor_sync(0xffffffffu, sg,  off, 16);
            sg2 += __shfl_xor_sync(0xffffffffu, sg2, off, 16);
        }
        float mc = sc * (1.f / 128.f);
        float vc = fmaxf(sc2 * (1.f / 128.f) - mc * mc, 0.f);
        float rc = rsqrtf(vc + 1e-5f);
        float mg = sg * (1.f / 128.f);
        float vg = fmaxf(sg2 * (1.f / 128.f) - mg * mg, 0.f);
        float rg = rsqrtf(vg + 1e-5f);

        float nlv[8];
#pragma unroll
        for (int j = 0; j < 8; j++) {
            int n = tn * 8 + j;
            float hc = (accc[r][j] - mc) * rc * __ldg(&lncg[n]) + __ldg(&lncb[n]);
            float hg = (accg[r][j] - mg) * rg * __ldg(&lngg[n]) + __ldg(&lngb[n]);
            nlv[j] = siluf_(hc) * sigmoidf_(hg);
        }
        float* np = g_nl + ((size_t)e << 7) + tn * 8;
        float4 o0 = make_float4(nlv[0], nlv[1], nlv[2], nlv[3]);
        float4 o1 = make_float4(nlv[4], nlv[5], nlv[6], nlv[7]);
        *(float4*)np = o0;
        *(float4*)(np + 4) = o1;

        float s0 = sw7[row][0], s1 = sw7[row][1], s2 = sw7[row][2], s3 = sw7[row][3];
        float s4 = sw7[row][4], s5 = sw7[row][5], s6 = sw7[row][6];
        float* ap = g_nodeagg + ((size_t)idxT[row] << 7);
#pragma unroll
        for (int j = 0; j < 8; j++) {
            int n = tn * 8 + j;
            float sw = s0 * Wenv_s[0][n] + s1 * Wenv_s[1][n] + s2 * Wenv_s[2][n]
                     + s3 * Wenv_s[3][n] + s4 * Wenv_s[4][n] + s5 * Wenv_s[5][n]
                     + s6 * Wenv_s[6][n];
            atomicAdd(ap + n, nlv[j] * sw);
        }
    }
}

// ---------------- kernel 3: delta_edge_dir = silu(nl@We1)@We2 -> atomic esum/cnt
__global__ __launch_bounds__(256) void k_edge_ffn(
    const float* __restrict__ We1, const float* __restrict__ We2,
    const int* __restrict__ d2u)
{
    __shared__ __align__(16) float As[16][64];
    __shared__ __align__(16) float Bs[16][128];
    __shared__ __align__(16) float t1[64][129];
    __shared__ int idxU[64];

    const int tid = threadIdx.x;
    const int eBase = blockIdx.x * 64;
    const int tm = tid >> 4, tn = tid & 15;
    if (tid < 64) idxU[tid] = d2u[eBase + tid];

    float acc[4][8];
#pragma unroll
    for (int r = 0; r < 4; r++)
#pragma unroll
        for (int j = 0; j < 8; j++) acc[r][j] = 0.f;

    __syncthreads();

    for (int k0 = 0; k0 < 128; k0 += 16) {
        {
            int m = tid >> 2;
            int kq = (tid & 3) << 2;
            float4 v = *(const float4*)(g_nl + ((size_t)(eBase + m) << 7) + k0 + kq);
            As[kq + 0][m] = v.x; As[kq + 1][m] = v.y; As[kq + 2][m] = v.z; As[kq + 3][m] = v.w;
        }
#pragma unroll
        for (int l = 0; l < 2; l++) {
            int flat = tid + l * 256;
            int kr = flat >> 5;
            int n = (flat & 31) << 2;
            *(float4*)&Bs[kr][n] = *(const float4*)(We1 + (size_t)(k0 + kr) * 128 + n);
        }
        __syncthreads();
#pragma unroll
        for (int kk = 0; kk < 16; kk++) {
            float4 a4 = *(const float4*)&As[kk][tm * 4];
            float a[4] = {a4.x, a4.y, a4.z, a4.w};
            float b[8];
            *(float4*)&b[0] = *(const float4*)&Bs[kk][tn * 8];
            *(float4*)&b[4] = *(const float4*)&Bs[kk][tn * 8 + 4];
#pragma unroll
            for (int r = 0; r < 4; r++)
#pragma unroll
                for (int j = 0; j < 8; j++) acc[r][j] = fmaf(a[r], b[j], acc[r][j]);
        }
        __syncthreads();
    }

#pragma unroll
    for (int r = 0; r < 4; r++)
#pragma unroll
        for (int j = 0; j < 8; j++) t1[tm * 4 + r][tn * 8 + j] = siluf_(acc[r][j]);
    __syncthreads();

    float acc2[4][8];
#pragma unroll
    for (int r = 0; r < 4; r++)
#pragma unroll
        for (int j = 0; j < 8; j++) acc2[r][j] = 0.f;

    for (int k0 = 0; k0 < 128; k0 += 16) {
#pragma unroll
        for (int l = 0; l < 2; l++) {
            int flat = tid + l * 256;
            int kr = flat >> 5;
            int n = (flat & 31) << 2;
            *(float4*)&Bs[kr][n] = *(const float4*)(We2 + (size_t)(k0 + kr) * 128 + n);
        }
        __syncthreads();
#pragma unroll
        for (int kk = 0; kk < 16; kk++) {
            float b[8];
            *(float4*)&b[0] = *(const float4*)&Bs[kk][tn * 8];
            *(float4*)&b[4] = *(const float4*)&Bs[kk][tn * 8 + 4];
#pragma unroll
            for (int r = 0; r < 4; r++) {
                float a = t1[tm * 4 + r][k0 + kk];
#pragma unroll
                for (int j = 0; j < 8; j++) acc2[r][j] = fmaf(a, b[j], acc2[r][j]);
            }
        }
        __syncthreads();
    }

#pragma unroll
    for (int r = 0; r < 4; r++) {
        int row = tm * 4 + r;
        int u = idxU[row];
        float* ep = g_esum + ((size_t)u << 7) + tn * 8;
#pragma unroll
        for (int j = 0; j < 8; j++) atomicAdd(ep + j, acc2[r][j]);
        if (tn == 0) atomicAdd(&g_cnt[u], 1.0f);
    }
}

// ---------------- kernel 4: delta_node = silu(agg@Wn1)@Wn2 + res, direct to out
__global__ __launch_bounds__(256) void k_node_ffn(
    const float* __restrict__ Wn1, const float* __restrict__ Wn2,
    const float* __restrict__ node_feat, const float* __restrict__ node_res_w,
    float* __restrict__ out_node)
{
    __shared__ __align__(16) float As[16][64];
    __shared__ __align__(16) float Bs[16][128];
    __shared__ __align__(16) float t1[64][129];

    const int tid = threadIdx.x;
    const int nBase = blockIdx.x * 64;
    const int tm = tid >> 4, tn = tid & 15;

    float acc[4][8];
#pragma unroll
    for (int r = 0; r < 4; r++)
#pragma unroll
        for (int j = 0; j < 8; j++) acc[r][j] = 0.f;

    for (int k0 = 0; k0 < 128; k0 += 16) {
        {
            int m = tid >> 2;
            int kq = (tid & 3) << 2;
            int row_g = nBase + m;
            float4 v = make_float4(0.f, 0.f, 0.f, 0.f);
            if (row_g < NN)
                v = *(const float4*)(g_nodeagg + ((size_t)row_g << 7) + k0 + kq);
            As[kq + 0][m] = v.x; As[kq + 1][m] = v.y; As[kq + 2][m] = v.z; As[kq + 3][m] = v.w;
        }
#pragma unroll
        for (int l = 0; l < 2; l++) {
            int flat = tid + l * 256;
            int kr = flat >> 5;
            int n = (flat & 31) << 2;
            *(float4*)&Bs[kr][n] = *(const float4*)(Wn1 + (size_t)(k0 + kr) * 128 + n);
        }
        __syncthreads();
#pragma unroll
        for (int kk = 0; kk < 16; kk++) {
            float4 a4 = *(const float4*)&As[kk][tm * 4];
            float a[4] = {a4.x, a4.y, a4.z, a4.w};
            float b[8];
            *(float4*)&b[0] = *(const float4*)&Bs[kk][tn * 8];
            *(float4*)&b[4] = *(const float4*)&Bs[kk][tn * 8 + 4];
#pragma unroll
            for (int r = 0; r < 4; r++)
#pragma unroll
                for (int j = 0; j < 8; j++) acc[r][j] = fmaf(a[r], b[j], acc[r][j]);
        }
        __syncthreads();
    }

#pragma unroll
    for (int r = 0; r < 4; r++)
#pragma unroll
        for (int j = 0; j < 8; j++) t1[tm * 4 + r][tn * 8 + j] = siluf_(acc[r][j]);
    __syncthreads();

    float acc2[4][8];
#pragma unroll
    for (int r = 0; r < 4; r++)
#pragma unroll
        for (int j = 0; j < 8; j++) acc2[r][j] = 0.f;

    for (int k0 = 0; k0 < 128; k0 += 16) {
#pragma unroll
        for (int l = 0; l < 2; l++) {
            int flat = tid + l * 256;
            int kr = flat >> 5;
            int n = (flat & 31) << 2;
            *(float4*)&Bs[kr][n] = *(const float4*)(Wn2 + (size_t)(k0 + kr) * 128 + n);
        }
        __syncthreads();
#pragma unroll
        for (int kk = 0; kk < 16; kk++) {
            float b[8];
            *(float4*)&b[0] = *(const float4*)&Bs[kk][tn * 8];
            *(float4*)&b[4] = *(const float4*)&Bs[kk][tn * 8 + 4];
#pragma unroll
            for (int r = 0; r < 4; r++) {
                float a = t1[tm * 4 + r][k0 + kk];
#pragma unroll
                for (int j = 0; j < 8; j++) acc2[r][j] = fmaf(a, b[j], acc2[r][j]);
            }
        }
        __syncthreads();
    }

#pragma unroll
    for (int r = 0; r < 4; r++) {
        int row = nBase + tm * 4 + r;
        if (row >= NN) continue;
        const float* nf = node_feat + ((size_t)row << 7) + tn * 8;
        float* op = out_node + ((size_t)row << 7) + tn * 8;
        float o[8];
#pragma unroll
        for (int j = 0; j < 8; j++) {
            int n = tn * 8 + j;
            o[j] = acc2[r][j] + __ldg(&node_res_w[n]) * nf[j];
        }
        *(float4*)op = make_float4(o[0], o[1], o[2], o[3]);
        *(float4*)(op + 4) = make_float4(o[4], o[5], o[6], o[7]);
    }
}

// ---------------- kernel 5: edge output = esum/max(cnt,1) + res*edge_feat
__global__ void k_edge_final(const float* __restrict__ edge_feat,
                             const float* __restrict__ edge_res_w,
                             float* __restrict__ out_edge)
{
    size_t i = (size_t)blockIdx.x * blockDim.x + threadIdx.x;
    const size_t total = (size_t)EUN * DD / 4;
    if (i >= total) return;
    size_t u = (i * 4) >> 7;
    int c = (int)((i * 4) & 127);
    float inv = __fdividef(1.0f, fmaxf(g_cnt[u], 1.0f));
    float4 es = ((const float4*)g_esum)[i];
    float4 ef = ((const float4*)edge_feat)[i];
    float4 rw = *(const float4*)&edge_res_w[c];
    float4 o;
    o.x = es.x * inv + rw.x * ef.x;
    o.y = es.y * inv + rw.y * ef.y;
    o.z = es.z * inv + rw.z * ef.z;
    o.w = es.w * inv + rw.w * ef.w;
    ((float4*)out_edge)[i] = o;
}

// ---------------- launch ----------------
extern "C" void kernel_launch(void* const* d_in, const int* in_sizes, int n_in,
                              void* d_out, int out_size)
{
    (void)in_sizes; (void)n_in; (void)out_size;
    const float* node_feat     = (const float*)d_in[0];
    const float* edge_feat     = (const float*)d_in[1];
    const float* smooth_weight = (const float*)d_in[2];
    const int*   source_index  = (const int*)d_in[3];
    const int*   target_index  = (const int*)d_in[4];
    const int*   d2u           = (const int*)d_in[5];
    const float* W_env         = (const float*)d_in[6];
    const float* Wc1           = (const float*)d_in[7];
    const float* Wc2           = (const float*)d_in[8];
    const float* Wg1           = (const float*)d_in[9];
    const float* Wg2           = (const float*)d_in[10];
    const float* ln_c_g        = (const float*)d_in[11];
    const float* ln_c_b        = (const float*)d_in[12];
    const float* ln_g_g        = (const float*)d_in[13];
    const float* ln_g_b        = (const float*)d_in[14];
    const float* Wn1           = (const float*)d_in[15];
    const float* Wn2           = (const float*)d_in[16];
    const float* We1           = (const float*)d_in[17];
    const float* We2           = (const float*)d_in[18];
    const float* node_res_w    = (const float*)d_in[19];
    const float* edge_res_w    = (const float*)d_in[20];

    float* out_node = (float*)d_out;
    float* out_edge = out_node + (size_t)NN * DD;

    k_zero<<<592, 256>>>();

    dim3 g1(EDN / 128, 2);
    k_gemm1<<<g1, 256>>>(node_feat, edge_feat, source_index, target_index, d2u, Wc1, Wg1);

    k_gemm2_ln<<<EDN / 64, 256>>>(Wc2, Wg2, ln_c_g, ln_c_b, ln_g_g, ln_g_b,
                                  smooth_weight, W_env, d2u, target_index);

    k_edge_ffn<<<EDN / 64, 256>>>(We1, We2, d2u);

    k_node_ffn<<<(NN + 63) / 64, 256>>>(Wn1, Wn2, node_feat, node_res_w, out_node);

    k_edge_final<<<(EUN * DD / 4 + 255) / 256, 256>>>(edge_feat, edge_res_w, out_edge);
}

// round 2
// speedup vs baseline: 1.6406x; 1.6406x over previous
#include <cuda_runtime.h>

#define NN  50000
#define EUN 200000
#define EDN 400000

// ---------------- scratch (device globals; no allocation) ----------------
__device__ __align__(16) float g_hc[EDN * 128];
__device__ __align__(16) float g_hg[EDN * 128];
__device__ __align__(16) float g_nl[EDN * 128];
__device__ __align__(16) float g_nodeagg[NN * 128];
__device__ __align__(16) float g_esum[EUN * 128];
__device__ __align__(16) float g_cnt[EUN];

__device__ __forceinline__ float sigmoidf_(float x) {
    return __fdividef(1.0f, 1.0f + __expf(-x));
}
__device__ __forceinline__ float siluf_(float x) {
    return x * sigmoidf_(x);
}
__device__ __forceinline__ unsigned f2tf(float f) {
    unsigned u;
    asm("cvt.rna.tf32.f32 %0, %1;" : "=r"(u) : "f"(f));
    return u;
}
__device__ __forceinline__ void mma8(float* d, const unsigned* a, const unsigned* b) {
    asm volatile(
        "mma.sync.aligned.m16n8k8.row.col.f32.tf32.tf32.f32 "
        "{%0,%1,%2,%3}, {%4,%5,%6,%7}, {%8,%9}, {%0,%1,%2,%3};"
        : "+f"(d[0]), "+f"(d[1]), "+f"(d[2]), "+f"(d[3])
        : "r"(a[0]), "r"(a[1]), "r"(a[2]), "r"(a[3]), "r"(b[0]), "r"(b[1]));
}

// ---------------- zero scratch accumulators ----------------
__global__ void k_zero() {
    size_t stride = (size_t)gridDim.x * blockDim.x;
    size_t i = (size_t)blockIdx.x * blockDim.x + threadIdx.x;
    float4 z = make_float4(0.f, 0.f, 0.f, 0.f);
    for (size_t p = i; p < (size_t)NN * 128 / 4; p += stride)  ((float4*)g_nodeagg)[p] = z;
    for (size_t p = i; p < (size_t)EUN * 128 / 4; p += stride) ((float4*)g_esum)[p] = z;
    for (size_t p = i; p < (size_t)EUN / 4; p += stride)       ((float4*)g_cnt)[p] = z;
}

// ============ kernel 1: gather-fused TF32 GEMM  h = silu(concat @ W1) ============
// block tile M=128, N=128, K=384 (ktile 32). 8 warps: 4m x 2n, warptile 32x64.
// grid.y: 0 -> Wc1 -> g_hc, 1 -> Wg1 -> g_hg
__global__ __launch_bounds__(256) void k_gemm1(
    const float* __restrict__ node_feat, const float* __restrict__ edge_feat,
    const int* __restrict__ src_i, const int* __restrict__ tgt_i, const int* __restrict__ d2u,
    const float* __restrict__ Wc1, const float* __restrict__ Wg1)
{
    __shared__ unsigned As[128 * 36];   // [row][k] stride 36
    __shared__ unsigned Bs[32 * 132];   // [k][n]   stride 132
    __shared__ int idxE[128], idxT[128], idxS[128];

    const int tid = threadIdx.x;
    const int eBase = blockIdx.x * 128;
    const float* __restrict__ W = (blockIdx.y == 0) ? Wc1 : Wg1;
    float* Out = (blockIdx.y == 0) ? g_hc : g_hg;

    if (tid < 128) { idxE[tid] = d2u[eBase + tid]; idxS[tid] = src_i[eBase + tid]; }
    else           { idxT[tid - 128] = tgt_i[eBase + tid - 128]; }

    const int w = tid >> 5, lane = tid & 31;
    const int wm = w & 3, wn = w >> 2;
    const int grp = lane >> 2, qid = lane & 3;

    float acc[2][8][4];
#pragma unroll
    for (int mi = 0; mi < 2; mi++)
#pragma unroll
        for (int ni = 0; ni < 8; ni++)
#pragma unroll
            for (int q = 0; q < 4; q++) acc[mi][ni][q] = 0.f;

    __syncthreads();

    for (int k0 = 0; k0 < 384; k0 += 32) {
        const int seg = k0 >> 7;
        const int kk0 = k0 & 127;
#pragma unroll
        for (int l = 0; l < 4; l++) {
            int f = tid + l * 256;
            int m = f >> 3, kq = (f & 7) << 2;
            const float* p;
            if (seg == 0)      p = edge_feat + ((size_t)idxE[m] << 7) + kk0 + kq;
            else if (seg == 1) p = node_feat + ((size_t)idxT[m] << 7) + kk0 + kq;
            else               p = node_feat + ((size_t)idxS[m] << 7) + kk0 + kq;
            float4 v = *(const float4*)p;
            uint4 q4 = make_uint4(f2tf(v.x), f2tf(v.y), f2tf(v.z), f2tf(v.w));
            *(uint4*)&As[m * 36 + kq] = q4;
        }
#pragma unroll
        for (int l = 0; l < 4; l++) {
            int f = tid + l * 256;
            int kr = f >> 5, n4 = (f & 31) << 2;
            float4 v = *(const float4*)(W + (size_t)(k0 + kr) * 128 + n4);
            *(uint4*)&Bs[kr * 132 + n4] = make_uint4(f2tf(v.x), f2tf(v.y), f2tf(v.z), f2tf(v.w));
        }
        __syncthreads();
#pragma unroll
        for (int k8 = 0; k8 < 32; k8 += 8) {
            unsigned a[2][4], b[8][2];
#pragma unroll
            for (int mi = 0; mi < 2; mi++) {
                int r = wm * 32 + mi * 16 + grp;
                a[mi][0] = As[r * 36 + k8 + qid];
                a[mi][1] = As[(r + 8) * 36 + k8 + qid];
                a[mi][2] = As[r * 36 + k8 + qid + 4];
                a[mi][3] = As[(r + 8) * 36 + k8 + qid + 4];
            }
#pragma unroll
            for (int ni = 0; ni < 8; ni++) {
                int c = wn * 64 + ni * 8 + grp;
                b[ni][0] = Bs[(k8 + qid) * 132 + c];
                b[ni][1] = Bs[(k8 + qid + 4) * 132 + c];
            }
#pragma unroll
            for (int mi = 0; mi < 2; mi++)
#pragma unroll
                for (int ni = 0; ni < 8; ni++) mma8(acc[mi][ni], a[mi], b[ni]);
        }
        __syncthreads();
    }

#pragma unroll
    for (int mi = 0; mi < 2; mi++) {
        int r0 = eBase + wm * 32 + mi * 16 + grp;
#pragma unroll
        for (int ni = 0; ni < 8; ni++) {
            int c = wn * 64 + ni * 8 + qid * 2;
            float2 v0 = make_float2(siluf_(acc[mi][ni][0]), siluf_(acc[mi][ni][1]));
            float2 v1 = make_float2(siluf_(acc[mi][ni][2]), siluf_(acc[mi][ni][3]));
            *(float2*)(Out + ((size_t)r0 << 7) + c) = v0;
            *(float2*)(Out + ((size_t)(r0 + 8) << 7) + c) = v1;
        }
    }
}

// ============ kernel 2: y = h @ W2 (core+gate), LN, silu*sig, envelope, node atomics
// block tile M=64, N=128, K=128 (ktile 16). 8 warps: 2m x 4n, warptile 32x32.
__global__ __launch_bounds__(256) void k_gemm2_ln(
    const float* __restrict__ Wc2, const float* __restrict__ Wg2,
    const float* __restrict__ lncg, const float* __restrict__ lncb,
    const float* __restrict__ lngg, const float* __restrict__ lngb,
    const float* __restrict__ smooth_weight, const float* __restrict__ W_env,
    const int* __restrict__ d2u, const int* __restrict__ tgt_i)
{
    __shared__ unsigned Ahc[64 * 20];
    __shared__ unsigned Ahg[64 * 20];
    __shared__ unsigned Bc[16 * 132];
    __shared__ unsigned Bg[16 * 132];
    __shared__ float Wenv_s[7][128];
    __shared__ float sw7[64][8];
    __shared__ int idxT[64];
    __shared__ float4 red[64][4];

    const int tid = threadIdx.x;
    const int eBase = blockIdx.x * 64;
    const int w = tid >> 5, lane = tid & 31;
    const int wm = w & 1, wn = w >> 1;
    const int grp = lane >> 2, qid = lane & 3;

    if (tid < 64) idxT[tid] = tgt_i[eBase + tid];
    for (int f = tid; f < 448; f += 256) {
        int m = f / 7, j = f % 7;
        sw7[m][j] = smooth_weight[(size_t)d2u[eBase + m] * 7 + j];
    }
    for (int f = tid; f < 896; f += 256) Wenv_s[f >> 7][f & 127] = W_env[f];

    float accc[2][4][4], accg[2][4][4];
#pragma unroll
    for (int mi = 0; mi < 2; mi++)
#pragma unroll
        for (int ni = 0; ni < 4; ni++)
#pragma unroll
            for (int q = 0; q < 4; q++) { accc[mi][ni][q] = 0.f; accg[mi][ni][q] = 0.f; }

    __syncthreads();

    for (int k0 = 0; k0 < 128; k0 += 16) {
        {
            int m = tid >> 2, kq = (tid & 3) << 2;
            float4 v = *(const float4*)(g_hc + ((size_t)(eBase + m) << 7) + k0 + kq);
            *(uint4*)&Ahc[m * 20 + kq] = make_uint4(f2tf(v.x), f2tf(v.y), f2tf(v.z), f2tf(v.w));
            float4 u = *(const float4*)(g_hg + ((size_t)(eBase + m) << 7) + k0 + kq);
            *(uint4*)&Ahg[m * 20 + kq] = make_uint4(f2tf(u.x), f2tf(u.y), f2tf(u.z), f2tf(u.w));
        }
#pragma unroll
        for (int l = 0; l < 2; l++) {
            int f = tid + l * 256;
            int kr = f >> 5, n4 = (f & 31) << 2;
            float4 v = *(const float4*)(Wc2 + (size_t)(k0 + kr) * 128 + n4);
            *(uint4*)&Bc[kr * 132 + n4] = make_uint4(f2tf(v.x), f2tf(v.y), f2tf(v.z), f2tf(v.w));
            float4 u = *(const float4*)(Wg2 + (size_t)(k0 + kr) * 128 + n4);
            *(uint4*)&Bg[kr * 132 + n4] = make_uint4(f2tf(u.x), f2tf(u.y), f2tf(u.z), f2tf(u.w));
        }
        __syncthreads();
#pragma unroll
        for (int k8 = 0; k8 < 16; k8 += 8) {
            unsigned ac[2][4], ag[2][4], bc[4][2], bg[4][2];
#pragma unroll
            for (int mi = 0; mi < 2; mi++) {
                int r = wm * 32 + mi * 16 + grp;
                ac[mi][0] = Ahc[r * 20 + k8 + qid];
                ac[mi][1] = Ahc[(r + 8) * 20 + k8 + qid];
                ac[mi][2] = Ahc[r * 20 + k8 + qid + 4];
                ac[mi][3] = Ahc[(r + 8) * 20 + k8 + qid + 4];
                ag[mi][0] = Ahg[r * 20 + k8 + qid];
                ag[mi][1] = Ahg[(r + 8) * 20 + k8 + qid];
                ag[mi][2] = Ahg[r * 20 + k8 + qid + 4];
                ag[mi][3] = Ahg[(r + 8) * 20 + k8 + qid + 4];
            }
#pragma unroll
            for (int ni = 0; ni < 4; ni++) {
                int c = wn * 32 + ni * 8 + grp;
                bc[ni][0] = Bc[(k8 + qid) * 132 + c];
                bc[ni][1] = Bc[(k8 + qid + 4) * 132 + c];
                bg[ni][0] = Bg[(k8 + qid) * 132 + c];
                bg[ni][1] = Bg[(k8 + qid + 4) * 132 + c];
            }
#pragma unroll
            for (int mi = 0; mi < 2; mi++)
#pragma unroll
                for (int ni = 0; ni < 4; ni++) {
                    mma8(accc[mi][ni], ac[mi], bc[ni]);
                    mma8(accg[mi][ni], ag[mi], bg[ni]);
                }
        }
        __syncthreads();
    }

    // ---- LN partials: per (row, warp-n) -> red ----
#pragma unroll
    for (int mi = 0; mi < 2; mi++)
#pragma unroll
        for (int h = 0; h < 2; h++) {
            int rloc = wm * 32 + mi * 16 + grp + 8 * h;
            float sc = 0.f, sc2 = 0.f, sg = 0.f, sg2 = 0.f;
#pragma unroll
            for (int ni = 0; ni < 4; ni++) {
                float c0 = accc[mi][ni][2 * h], c1 = accc[mi][ni][2 * h + 1];
                float g0 = accg[mi][ni][2 * h], g1 = accg[mi][ni][2 * h + 1];
                sc += c0 + c1; sc2 += c0 * c0 + c1 * c1;
                sg += g0 + g1; sg2 += g0 * g0 + g1 * g1;
            }
#pragma unroll
            for (int off = 1; off < 4; off <<= 1) {
                sc  += __shfl_xor_sync(0xffffffffu, sc,  off, 4);
                sc2 += __shfl_xor_sync(0xffffffffu, sc2, off, 4);
                sg  += __shfl_xor_sync(0xffffffffu, sg,  off, 4);
                sg2 += __shfl_xor_sync(0xffffffffu, sg2, off, 4);
            }
            if (qid == 0) red[rloc][wn] = make_float4(sc, sc2, sg, sg2);
        }
    __syncthreads();

    // ---- epilogue ----
#pragma unroll
    for (int mi = 0; mi < 2; mi++)
#pragma unroll
        for (int h = 0; h < 2; h++) {
            int rloc = wm * 32 + mi * 16 + grp + 8 * h;
            float4 p0 = red[rloc][0], p1 = red[rloc][1], p2 = red[rloc][2], p3 = red[rloc][3];
            float sc = p0.x + p1.x + p2.x + p3.x;
            float sc2 = p0.y + p1.y + p2.y + p3.y;
            float sg = p0.z + p1.z + p2.z + p3.z;
            float sg2 = p0.w + p1.w + p2.w + p3.w;
            float mc = sc * (1.f / 128.f);
            float vc = fmaxf(sc2 * (1.f / 128.f) - mc * mc, 0.f);
            float rc = rsqrtf(vc + 1e-5f);
            float mg = sg * (1.f / 128.f);
            float vg = fmaxf(sg2 * (1.f / 128.f) - mg * mg, 0.f);
            float rg = rsqrtf(vg + 1e-5f);

            int e = eBase + rloc;
            float s0 = sw7[rloc][0], s1 = sw7[rloc][1], s2 = sw7[rloc][2], s3 = sw7[rloc][3];
            float s4 = sw7[rloc][4], s5 = sw7[rloc][5], s6 = sw7[rloc][6];
            float* ap = g_nodeagg + ((size_t)idxT[rloc] << 7);
            float* np = g_nl + ((size_t)e << 7);
#pragma unroll
            for (int ni = 0; ni < 4; ni++) {
                int c = wn * 32 + ni * 8 + qid * 2;
                float nl0, nl1;
                {
                    float hc = (accc[mi][ni][2 * h] - mc) * rc * __ldg(&lncg[c]) + __ldg(&lncb[c]);
                    float hg = (accg[mi][ni][2 * h] - mg) * rg * __ldg(&lngg[c]) + __ldg(&lngb[c]);
                    nl0 = siluf_(hc) * sigmoidf_(hg);
                    float hc1 = (accc[mi][ni][2 * h + 1] - mc) * rc * __ldg(&lncg[c + 1]) + __ldg(&lncb[c + 1]);
                    float hg1 = (accg[mi][ni][2 * h + 1] - mg) * rg * __ldg(&lngg[c + 1]) + __ldg(&lngb[c + 1]);
                    nl1 = siluf_(hc1) * sigmoidf_(hg1);
                }
                *(float2*)(np + c) = make_float2(nl0, nl1);
                float sw0 = s0 * Wenv_s[0][c] + s1 * Wenv_s[1][c] + s2 * Wenv_s[2][c]
                          + s3 * Wenv_s[3][c] + s4 * Wenv_s[4][c] + s5 * Wenv_s[5][c]
                          + s6 * Wenv_s[6][c];
                float sw1 = s0 * Wenv_s[0][c + 1] + s1 * Wenv_s[1][c + 1] + s2 * Wenv_s[2][c + 1]
                          + s3 * Wenv_s[3][c + 1] + s4 * Wenv_s[4][c + 1] + s5 * Wenv_s[5][c + 1]
                          + s6 * Wenv_s[6][c + 1];
                atomicAdd(ap + c, nl0 * sw0);
                atomicAdd(ap + c + 1, nl1 * sw1);
            }
        }
}

// ============ kernel 3: delta_edge_dir = silu(nl@We1)@We2 -> atomic esum/cnt
// block M=64, N=128, chained two-stage TF32 GEMM; warps 2m x 4n, warptile 32x32.
__global__ __launch_bounds__(256) void k_edge_ffn(
    const float* __restrict__ We1, const float* __restrict__ We2,
    const int* __restrict__ d2u)
{
    __shared__ unsigned As[64 * 20];
    __shared__ unsigned Bs[16 * 132];
    __shared__ unsigned t1[64 * 132];   // silu(stage1) in A-frag layout [row][k]
    __shared__ int idxU[64];

    const int tid = threadIdx.x;
    const int eBase = blockIdx.x * 64;
    const int w = tid >> 5, lane = tid & 31;
    const int wm = w & 1, wn = w >> 1;
    const int grp = lane >> 2, qid = lane & 3;

    if (tid < 64) idxU[tid] = d2u[eBase + tid];

    float acc[2][4][4];
#pragma unroll
    for (int mi = 0; mi < 2; mi++)
#pragma unroll
        for (int ni = 0; ni < 4; ni++)
#pragma unroll
            for (int q = 0; q < 4; q++) acc[mi][ni][q] = 0.f;

    __syncthreads();

    // stage 1: silu(nl @ We1)
    for (int k0 = 0; k0 < 128; k0 += 16) {
        {
            int m = tid >> 2, kq = (tid & 3) << 2;
            float4 v = *(const float4*)(g_nl + ((size_t)(eBase + m) << 7) + k0 + kq);
            *(uint4*)&As[m * 20 + kq] = make_uint4(f2tf(v.x), f2tf(v.y), f2tf(v.z), f2tf(v.w));
        }
#pragma unroll
        for (int l = 0; l < 2; l++) {
            int f = tid + l * 256;
            int kr = f >> 5, n4 = (f & 31) << 2;
            float4 v = *(const float4*)(We1 + (size_t)(k0 + kr) * 128 + n4);
            *(uint4*)&Bs[kr * 132 + n4] = make_uint4(f2tf(v.x), f2tf(v.y), f2tf(v.z), f2tf(v.w));
        }
        __syncthreads();
#pragma unroll
        for (int k8 = 0; k8 < 16; k8 += 8) {
            unsigned a[2][4], b[4][2];
#pragma unroll
            for (int mi = 0; mi < 2; mi++) {
                int r = wm * 32 + mi * 16 + grp;
                a[mi][0] = As[r * 20 + k8 + qid];
                a[mi][1] = As[(r + 8) * 20 + k8 + qid];
                a[mi][2] = As[r * 20 + k8 + qid + 4];
                a[mi][3] = As[(r + 8) * 20 + k8 + qid + 4];
            }
#pragma unroll
            for (int ni = 0; ni < 4; ni++) {
                int c = wn * 32 + ni * 8 + grp;
                b[ni][0] = Bs[(k8 + qid) * 132 + c];
                b[ni][1] = Bs[(k8 + qid + 4) * 132 + c];
            }
#pragma unroll
            for (int mi = 0; mi < 2; mi++)
#pragma unroll
                for (int ni = 0; ni < 4; ni++) mma8(acc[mi][ni], a[mi], b[ni]);
        }
        __syncthreads();
    }
    // write silu(acc) into t1 in [row][k] layout
#pragma unroll
    for (int mi = 0; mi < 2; mi++)
#pragma unroll
        for (int h = 0; h < 2; h++) {
            int r = wm * 32 + mi * 16 + grp + 8 * h;
#pragma unroll
            for (int ni = 0; ni < 4; ni++) {
                int c = wn * 32 + ni * 8 + qid * 2;
                t1[r * 132 + c]     = f2tf(siluf_(acc[mi][ni][2 * h]));
                t1[r * 132 + c + 1] = f2tf(siluf_(acc[mi][ni][2 * h + 1]));
            }
        }
    __syncthreads();

    // stage 2: t1 @ We2
    float acc2[2][4][4];
#pragma unroll
    for (int mi = 0; mi < 2; mi++)
#pragma unroll
        for (int ni = 0; ni < 4; ni++)
#pragma unroll
            for (int q = 0; q < 4; q++) acc2[mi][ni][q] = 0.f;

    for (int k0 = 0; k0 < 128; k0 += 16) {
#pragma unroll
        for (int l = 0; l < 2; l++) {
            int f = tid + l * 256;
            int kr = f >> 5, n4 = (f & 31) << 2;
            float4 v = *(const float4*)(We2 + (size_t)(k0 + kr) * 128 + n4);
            *(uint4*)&Bs[kr * 132 + n4] = make_uint4(f2tf(v.x), f2tf(v.y), f2tf(v.z), f2tf(v.w));
        }
        __syncthreads();
#pragma unroll
        for (int k8 = 0; k8 < 16; k8 += 8) {
            unsigned a[2][4], b[4][2];
#pragma unroll
            for (int mi = 0; mi < 2; mi++) {
                int r = wm * 32 + mi * 16 + grp;
                a[mi][0] = t1[r * 132 + k0 + k8 + qid];
                a[mi][1] = t1[(r + 8) * 132 + k0 + k8 + qid];
                a[mi][2] = t1[r * 132 + k0 + k8 + qid + 4];
                a[mi][3] = t1[(r + 8) * 132 + k0 + k8 + qid + 4];
            }
#pragma unroll
            for (int ni = 0; ni < 4; ni++) {
                int c = wn * 32 + ni * 8 + grp;
                b[ni][0] = Bs[(k8 + qid) * 132 + c];
                b[ni][1] = Bs[(k8 + qid + 4) * 132 + c];
            }
#pragma unroll
            for (int mi = 0; mi < 2; mi++)
#pragma unroll
                for (int ni = 0; ni < 4; ni++) mma8(acc2[mi][ni], a[mi], b[ni]);
        }
        __syncthreads();
    }

#pragma unroll
    for (int mi = 0; mi < 2; mi++)
#pragma unroll
        for (int h = 0; h < 2; h++) {
            int rloc = wm * 32 + mi * 16 + grp + 8 * h;
            int u = idxU[rloc];
            float* ep = g_esum + ((size_t)u << 7);
#pragma unroll
            for (int ni = 0; ni < 4; ni++) {
                int c = wn * 32 + ni * 8 + qid * 2;
                atomicAdd(ep + c,     acc2[mi][ni][2 * h]);
                atomicAdd(ep + c + 1, acc2[mi][ni][2 * h + 1]);
            }
            if (wn == 0 && qid == 0) atomicAdd(&g_cnt[u], 1.0f);
        }
}

// ============ kernel 4: delta_node = silu(agg@Wn1)@Wn2 + res -> out_node
__global__ __launch_bounds__(256) void k_node_ffn(
    const float* __restrict__ Wn1, const float* __restrict__ Wn2,
    const float* __restrict__ node_feat, const float* __restrict__ node_res_w,
    float* __restrict__ out_node)
{
    __shared__ unsigned As[64 * 20];
    __shared__ unsigned Bs[16 * 132];
    __shared__ unsigned t1[64 * 132];

    const int tid = threadIdx.x;
    const int nBase = blockIdx.x * 64;
    const int w = tid >> 5, lane = tid & 31;
    const int wm = w & 1, wn = w >> 1;
    const int grp = lane >> 2, qid = lane & 3;

    float acc[2][4][4];
#pragma unroll
    for (int mi = 0; mi < 2; mi++)
#pragma unroll
        for (int ni = 0; ni < 4; ni++)
#pragma unroll
            for (int q = 0; q < 4; q++) acc[mi][ni][q] = 0.f;

    for (int k0 = 0; k0 < 128; k0 += 16) {
        {
            int m = tid >> 2, kq = (tid & 3) << 2;
            int rg_ = nBase + m;
            uint4 q4 = make_uint4(0u, 0u, 0u, 0u);
            if (rg_ < NN) {
                float4 v = *(const float4*)(g_nodeagg + ((size_t)rg_ << 7) + k0 + kq);
                q4 = make_uint4(f2tf(v.x), f2tf(v.y), f2tf(v.z), f2tf(v.w));
            }
            *(uint4*)&As[m * 20 + kq] = q4;
        }
#pragma unroll
        for (int l = 0; l < 2; l++) {
            int f = tid + l * 256;
            int kr = f >> 5, n4 = (f & 31) << 2;
            float4 v = *(const float4*)(Wn1 + (size_t)(k0 + kr) * 128 + n4);
            *(uint4*)&Bs[kr * 132 + n4] = make_uint4(f2tf(v.x), f2tf(v.y), f2tf(v.z), f2tf(v.w));
        }
        __syncthreads();
#pragma unroll
        for (int k8 = 0; k8 < 16; k8 += 8) {
            unsigned a[2][4], b[4][2];
#pragma unroll
            for (int mi = 0; mi < 2; mi++) {
                int r = wm * 32 + mi * 16 + grp;
                a[mi][0] = As[r * 20 + k8 + qid];
                a[mi][1] = As[(r + 8) * 20 + k8 + qid];
                a[mi][2] = As[r * 20 + k8 + qid + 4];
                a[mi][3] = As[(r + 8) * 20 + k8 + qid + 4];
            }
#pragma unroll
            for (int ni = 0; ni < 4; ni++) {
                int c = wn * 32 + ni * 8 + grp;
                b[ni][0] = Bs[(k8 + qid) * 132 + c];
                b[ni][1] = Bs[(k8 + qid + 4) * 132 + c];
            }
#pragma unroll
            for (int mi = 0; mi < 2; mi++)
#pragma unroll
                for (int ni = 0; ni < 4; ni++) mma8(acc[mi][ni], a[mi], b[ni]);
        }
        __syncthreads();
    }
#pragma unroll
    for (int mi = 0; mi < 2; mi++)
#pragma unroll
        for (int h = 0; h < 2; h++) {
            int r = wm * 32 + mi * 16 + grp + 8 * h;
#pragma unroll
            for (int ni = 0; ni < 4; ni++) {
                int c = wn * 32 + ni * 8 + qid * 2;
                t1[r * 132 + c]     = f2tf(siluf_(acc[mi][ni][2 * h]));
                t1[r * 132 + c + 1] = f2tf(siluf_(acc[mi][ni][2 * h + 1]));
            }
        }
    __syncthreads();

    float acc2[2][4][4];
#pragma unroll
    for (int mi = 0; mi < 2; mi++)
#pragma unroll
        for (int ni = 0; ni < 4; ni++)
#pragma unroll
            for (int q = 0; q < 4; q++) acc2[mi][ni][q] = 0.f;

    for (int k0 = 0; k0 < 128; k0 += 16) {
#pragma unroll
        for (int l = 0; l < 2; l++) {
            int f = tid + l * 256;
            int kr = f >> 5, n4 = (f & 31) << 2;
            float4 v = *(const float4*)(Wn2 + (size_t)(k0 + kr) * 128 + n4);
            *(uint4*)&Bs[kr * 132 + n4] = make_uint4(f2tf(v.x), f2tf(v.y), f2tf(v.z), f2tf(v.w));
        }
        __syncthreads();
#pragma unroll
        for (int k8 = 0; k8 < 16; k8 += 8) {
            unsigned a[2][4], b[4][2];
#pragma unroll
            for (int mi = 0; mi < 2; mi++) {
                int r = wm * 32 + mi * 16 + grp;
                a[mi][0] = t1[r * 132 + k0 + k8 + qid];
                a[mi][1] = t1[(r + 8) * 132 + k0 + k8 + qid];
                a[mi][2] = t1[r * 132 + k0 + k8 + qid + 4];
                a[mi][3] = t1[(r + 8) * 132 + k0 + k8 + qid + 4];
            }
#pragma unroll
            for (int ni = 0; ni < 4; ni++) {
                int c = wn * 32 + ni * 8 + grp;
                b[ni][0] = Bs[(k8 + qid) * 132 + c];
                b[ni][1] = Bs[(k8 + qid + 4) * 132 + c];
            }
#pragma unroll
            for (int mi = 0; mi < 2; mi++)
#pragma unroll
                for (int ni = 0; ni < 4; ni++) mma8(acc2[mi][ni], a[mi], b[ni]);
        }
        __syncthreads();
    }

#pragma unroll
    for (int mi = 0; mi < 2; mi++)
#pragma unroll
        for (int h = 0; h < 2; h++) {
            int rg_ = nBase + wm * 32 + mi * 16 + grp + 8 * h;
            if (rg_ >= NN) continue;
            const float* nf = node_feat + ((size_t)rg_ << 7);
            float* op = out_node + ((size_t)rg_ << 7);
#pragma unroll
            for (int ni = 0; ni < 4; ni++) {
                int c = wn * 32 + ni * 8 + qid * 2;
                float o0 = acc2[mi][ni][2 * h]     + __ldg(&node_res_w[c])     * nf[c];
                float o1 = acc2[mi][ni][2 * h + 1] + __ldg(&node_res_w[c + 1]) * nf[c + 1];
                *(float2*)(op + c) = make_float2(o0, o1);
            }
        }
}

// ============ kernel 5: edge output = esum/max(cnt,1) + res*edge_feat
__global__ void k_edge_final(const float* __restrict__ edge_feat,
                             const float* __restrict__ edge_res_w,
                             float* __restrict__ out_edge)
{
    size_t i = (size_t)blockIdx.x * blockDim.x + threadIdx.x;
    const size_t total = (size_t)EUN * 128 / 4;
    if (i >= total) return;
    size_t u = (i * 4) >> 7;
    int c = (int)((i * 4) & 127);
    float inv = __fdividef(1.0f, fmaxf(g_cnt[u], 1.0f));
    float4 es = ((const float4*)g_esum)[i];
    float4 ef = ((const float4*)edge_feat)[i];
    float4 rw = *(const float4*)&edge_res_w[c];
    float4 o;
    o.x = es.x * inv + rw.x * ef.x;
    o.y = es.y * inv + rw.y * ef.y;
    o.z = es.z * inv + rw.z * ef.z;
    o.w = es.w * inv + rw.w * ef.w;
    ((float4*)out_edge)[i] = o;
}

// ---------------- launch ----------------
extern "C" void kernel_launch(void* const* d_in, const int* in_sizes, int n_in,
                              void* d_out, int out_size)
{
    (void)in_sizes; (void)n_in; (void)out_size;
    const float* node_feat     = (const float*)d_in[0];
    const float* edge_feat     = (const float*)d_in[1];
    const float* smooth_weight = (const float*)d_in[2];
    const int*   source_index  = (const int*)d_in[3];
    const int*   target_index  = (const int*)d_in[4];
    const int*   d2u           = (const int*)d_in[5];
    const float* W_env         = (const float*)d_in[6];
    const float* Wc1           = (const float*)d_in[7];
    const float* Wc2           = (const float*)d_in[8];
    const float* Wg1           = (const float*)d_in[9];
    const float* Wg2           = (const float*)d_in[10];
    const float* ln_c_g        = (const float*)d_in[11];
    const float* ln_c_b        = (const float*)d_in[12];
    const float* ln_g_g        = (const float*)d_in[13];
    const float* ln_g_b        = (const float*)d_in[14];
    const float* Wn1           = (const float*)d_in[15];
    const float* Wn2           = (const float*)d_in[16];
    const float* We1           = (const float*)d_in[17];
    const float* We2           = (const float*)d_in[18];
    const float* node_res_w    = (const float*)d_in[19];
    const float* edge_res_w    = (const float*)d_in[20];

    float* out_node = (float*)d_out;
    float* out_edge = out_node + (size_t)NN * 128;

    k_zero<<<592, 256>>>();

    dim3 g1(EDN / 128, 2);
    k_gemm1<<<g1, 256>>>(node_feat, edge_feat, source_index, target_index, d2u, Wc1, Wg1);

    k_gemm2_ln<<<EDN / 64, 256>>>(Wc2, Wg2, ln_c_g, ln_c_b, ln_g_g, ln_g_b,
                                  smooth_weight, W_env, d2u, target_index);

    k_edge_ffn<<<EDN / 64, 256>>>(We1, We2, d2u);

    k_node_ffn<<<(NN + 63) / 64, 256>>>(Wn1, Wn2, node_feat, node_res_w, out_node);

    k_edge_final<<<(EUN * 128 / 4 + 255) / 256, 256>>>(edge_feat, edge_res_w, out_edge);
}

// round 3
// speedup vs baseline: 3.8130x; 2.3241x over previous
#include <cuda_runtime.h>
#include <cuda_fp16.h>

#define NN  50000
#define EUN 200000
#define EDN 400000

// ---------------- scratch (device globals; no allocation) ----------------
// half2-packed intermediates: [row][64] u32 words (128 halves)
__device__ __align__(16) unsigned g_hc[EDN * 64];
__device__ __align__(16) unsigned g_hg[EDN * 64];
__device__ __align__(16) unsigned g_nl[EDN * 64];
__device__ __align__(16) float g_nodeagg[NN * 128];
__device__ __align__(16) float g_esum[EUN * 128];
__device__ __align__(16) float g_cnt[EUN];

// pre-transposed fp16 weights, tile-blocked: [ktile][n][16 words], ktile = 32 k (16 kpairs)
__device__ __align__(16) unsigned g_w1t[12 * 256 * 16];   // Wc1|Wg1 merged: n 0..255, K=384
__device__ __align__(16) unsigned g_w2ct[4 * 128 * 16];   // Wc2
__device__ __align__(16) unsigned g_w2gt[4 * 128 * 16];   // Wg2
__device__ __align__(16) unsigned g_we1t[4 * 128 * 16];
__device__ __align__(16) unsigned g_we2t[4 * 128 * 16];
__device__ __align__(16) unsigned g_wn1t[4 * 128 * 16];
__device__ __align__(16) unsigned g_wn2t[4 * 128 * 16];

__device__ __forceinline__ float sigmoidf_(float x) {
    return __fdividef(1.0f, 1.0f + __expf(-x));
}
__device__ __forceinline__ float siluf_(float x) { return x * sigmoidf_(x); }

__device__ __forceinline__ unsigned pack2(float x, float y) {
    __half2 h = __floats2half2_rn(make_float2(x, y).x, make_float2(x, y).y);
    return *reinterpret_cast<unsigned*>(&h);
}
__device__ __forceinline__ unsigned sptr(const void* p) {
    return (unsigned)__cvta_generic_to_shared(p);
}
__device__ __forceinline__ void ldsm4(unsigned* r, unsigned a) {
    asm volatile("ldmatrix.sync.aligned.m8n8.x4.shared.b16 {%0,%1,%2,%3}, [%4];"
        : "=r"(r[0]), "=r"(r[1]), "=r"(r[2]), "=r"(r[3]) : "r"(a));
}
__device__ __forceinline__ void ldsm2(unsigned* r, unsigned a) {
    asm volatile("ldmatrix.sync.aligned.m8n8.x2.shared.b16 {%0,%1}, [%2];"
        : "=r"(r[0]), "=r"(r[1]) : "r"(a));
}
__device__ __forceinline__ void mma16(float* d, const unsigned* a, const unsigned* b) {
    asm volatile(
        "mma.sync.aligned.m16n8k16.row.col.f32.f16.f16.f32 "
        "{%0,%1,%2,%3}, {%4,%5,%6,%7}, {%8,%9}, {%0,%1,%2,%3};"
        : "+f"(d[0]), "+f"(d[1]), "+f"(d[2]), "+f"(d[3])
        : "r"(a[0]), "r"(a[1]), "r"(a[2]), "r"(a[3]), "r"(b[0]), "r"(b[1]));
}

// ---------------- weight prep: fp32 [K][128] -> fp16 transposed tile-blocked ----------------
__global__ void k_prep(const float* __restrict__ Wc1, const float* __restrict__ Wg1,
                       const float* __restrict__ Wc2, const float* __restrict__ Wg2,
                       const float* __restrict__ We1, const float* __restrict__ We2,
                       const float* __restrict__ Wn1, const float* __restrict__ Wn2)
{
    int i = blockIdx.x * blockDim.x + threadIdx.x;
    if (i < 12 * 256 * 16) {
        int kt = i >> 12;          // /4096
        int r = i & 4095;
        int n = r >> 4, kpl = r & 15;
        int kp = kt * 16 + kpl;
        const float* W = (n < 128) ? Wc1 : Wg1;
        int c = n & 127;
        g_w1t[i] = pack2(W[(size_t)(2 * kp) * 128 + c], W[(size_t)(2 * kp + 1) * 128 + c]);
        return;
    }
    int j = i - 12 * 256 * 16;
    if (j < 6 * 8192) {
        int mtx = j >> 13;
        int r = j & 8191;
        int kt = r >> 11, rr = r & 2047;
        int n = rr >> 4, kpl = rr & 15;
        int kp = kt * 16 + kpl;
        const float* W; unsigned* O;
        switch (mtx) {
            case 0: W = Wc2; O = g_w2ct; break;
            case 1: W = Wg2; O = g_w2gt; break;
            case 2: W = We1; O = g_we1t; break;
            case 3: W = We2; O = g_we2t; break;
            case 4: W = Wn1; O = g_wn1t; break;
            default: W = Wn2; O = g_wn2t; break;
        }
        O[r] = pack2(W[(size_t)(2 * kp) * 128 + n], W[(size_t)(2 * kp + 1) * 128 + n]);
    }
}

// ---------------- zero scratch accumulators ----------------
__global__ void k_zero() {
    size_t stride = (size_t)gridDim.x * blockDim.x;
    size_t i = (size_t)blockIdx.x * blockDim.x + threadIdx.x;
    float4 z = make_float4(0.f, 0.f, 0.f, 0.f);
    for (size_t p = i; p < (size_t)NN * 128 / 4; p += stride)  ((float4*)g_nodeagg)[p] = z;
    for (size_t p = i; p < (size_t)EUN * 128 / 4; p += stride) ((float4*)g_esum)[p] = z;
    for (size_t p = i; p < (size_t)EUN / 4; p += stride)       ((float4*)g_cnt)[p] = z;
}

// ============ kernel 1: gather-fused f16 GEMM  [hc|hg] = silu(concat @ [Wc1|Wg1]) ============
// block M=64, N=256, K=384, ktile=32. 8 warps: 2m x 4n, warptile 32x64 (mi=2, ni=8).
__global__ __launch_bounds__(256) void k_gemm1(
    const float* __restrict__ node_feat, const float* __restrict__ edge_feat,
    const int* __restrict__ src_i, const int* __restrict__ tgt_i, const int* __restrict__ d2u)
{
    __shared__ __align__(16) unsigned As[64 * 20];    // [m][kpair] pitch 20
    __shared__ __align__(16) unsigned Bs[256 * 20];   // [n][kpair] pitch 20
    __shared__ int idxE[64], idxT[64], idxS[64];

    const int tid = threadIdx.x;
    const int eBase = blockIdx.x * 64;
    if (tid < 64)       idxE[tid] = d2u[eBase + tid];
    else if (tid < 128) idxT[tid - 64] = tgt_i[eBase + tid - 64];
    else if (tid < 192) idxS[tid - 128] = src_i[eBase + tid - 128];

    const int w = tid >> 5, lane = tid & 31;
    const int wm = w & 1, wn = w >> 1;
    const int grp = lane >> 2, qid = lane & 3;

    const int aRow = wm * 32 + (lane & 7) + ((lane >> 3) & 1) * 8;
    const int aCol = ((lane >> 4) & 1) * 4;
    const unsigned aBase = sptr(As) + (aRow * 20 + aCol) * 4;
    const unsigned bBase = sptr(Bs) + ((wn * 64 + (lane & 7)) * 20 + ((lane >> 3) & 1) * 4) * 4;

    float acc[2][8][4];
#pragma unroll
    for (int mi = 0; mi < 2; mi++)
#pragma unroll
        for (int ni = 0; ni < 8; ni++)
#pragma unroll
            for (int q = 0; q < 4; q++) acc[mi][ni][q] = 0.f;

    __syncthreads();

    for (int kt = 0; kt < 12; kt++) {
        const int k0 = kt * 32;
        // fill A: m = tid>>2, k8 = (tid&3)*8 halves
        {
            int m = tid >> 2, k8 = (tid & 3) * 8;
            int gk = k0 + k8;
            int seg = gk >> 7, kk = gk & 127;
            int idx = (seg == 0) ? idxE[m] : (seg == 1 ? idxT[m] : idxS[m]);
            const float* p = ((seg == 0) ? edge_feat : node_feat) + ((size_t)idx << 7) + kk;
            float4 v0 = *(const float4*)p;
            float4 v1 = *(const float4*)(p + 4);
            *(uint4*)&As[m * 20 + (k8 >> 1)] =
                make_uint4(pack2(v0.x, v0.y), pack2(v0.z, v0.w), pack2(v1.x, v1.y), pack2(v1.z, v1.w));
        }
        // fill B: flat copy from tile-blocked g_w1t
        {
            const uint4* src = (const uint4*)&g_w1t[kt * 4096];
#pragma unroll
            for (int l = 0; l < 4; l++) {
                int i4 = tid + l * 256;
                int n = i4 >> 2, wq = (i4 & 3) * 4;
                *(uint4*)&Bs[n * 20 + wq] = src[i4];
            }
        }
        __syncthreads();
#pragma unroll
        for (int k16 = 0; k16 < 2; k16++) {
            unsigned a[2][4], b[8][2];
#pragma unroll
            for (int mi = 0; mi < 2; mi++) ldsm4(a[mi], aBase + (mi * 16 * 20 + k16 * 8) * 4);
#pragma unroll
            for (int ni = 0; ni < 8; ni++) ldsm2(b[ni], bBase + (ni * 8 * 20 + k16 * 8) * 4);
#pragma unroll
            for (int mi = 0; mi < 2; mi++)
#pragma unroll
                for (int ni = 0; ni < 8; ni++) mma16(acc[mi][ni], a[mi], b[ni]);
        }
        __syncthreads();
    }

#pragma unroll
    for (int mi = 0; mi < 2; mi++)
#pragma unroll
        for (int h = 0; h < 2; h++) {
            size_t row = eBase + wm * 32 + mi * 16 + grp + 8 * h;
#pragma unroll
            for (int ni = 0; ni < 8; ni++) {
                int c = wn * 64 + ni * 8 + qid * 2;
                unsigned v = pack2(siluf_(acc[mi][ni][2 * h]), siluf_(acc[mi][ni][2 * h + 1]));
                if (c < 128) g_hc[row * 64 + (c >> 1)] = v;
                else         g_hg[row * 64 + (c >> 1) - 64] = v;
            }
        }
}

// ============ kernel 2: y = h @ W2 (core+gate), LN, silu*sig, envelope, node atomics
// block M=64, N=128 per matrix, K=128, ktile=32. warps 2m x 4n, warptile 32x32 per matrix.
__global__ __launch_bounds__(256) void k_gemm2_ln(
    const float* __restrict__ lncg, const float* __restrict__ lncb,
    const float* __restrict__ lngg, const float* __restrict__ lngb,
    const float* __restrict__ smooth_weight, const float* __restrict__ W_env,
    const int* __restrict__ d2u, const int* __restrict__ tgt_i)
{
    __shared__ __align__(16) unsigned Ac[64 * 20];
    __shared__ __align__(16) unsigned Ag[64 * 20];
    __shared__ __align__(16) unsigned Bc[128 * 20];
    __shared__ __align__(16) unsigned Bg[128 * 20];
    __shared__ float Wenv_s[7][128];
    __shared__ float sw7[64][8];
    __shared__ int idxT[64];
    __shared__ float4 red[64][4];

    const int tid = threadIdx.x;
    const int eBase = blockIdx.x * 64;
    const int w = tid >> 5, lane = tid & 31;
    const int wm = w & 1, wn = w >> 1;
    const int grp = lane >> 2, qid = lane & 3;

    if (tid < 64) idxT[tid] = tgt_i[eBase + tid];
    for (int f = tid; f < 448; f += 256) {
        int m = f / 7, j = f % 7;
        sw7[m][j] = smooth_weight[(size_t)d2u[eBase + m] * 7 + j];
    }
    for (int f = tid; f < 896; f += 256) Wenv_s[f >> 7][f & 127] = W_env[f];

    const int aRow = wm * 32 + (lane & 7) + ((lane >> 3) & 1) * 8;
    const int aCol = ((lane >> 4) & 1) * 4;
    const unsigned aBaseC = sptr(Ac) + (aRow * 20 + aCol) * 4;
    const unsigned aBaseG = sptr(Ag) + (aRow * 20 + aCol) * 4;
    const unsigned bOff = ((wn * 32 + (lane & 7)) * 20 + ((lane >> 3) & 1) * 4) * 4;
    const unsigned bBaseC = sptr(Bc) + bOff;
    const unsigned bBaseG = sptr(Bg) + bOff;

    float accc[2][4][4], accg[2][4][4];
#pragma unroll
    for (int mi = 0; mi < 2; mi++)
#pragma unroll
        for (int ni = 0; ni < 4; ni++)
#pragma unroll
            for (int q = 0; q < 4; q++) { accc[mi][ni][q] = 0.f; accg[mi][ni][q] = 0.f; }

    __syncthreads();

    for (int kt = 0; kt < 4; kt++) {
        {   // A fills: raw copies from half2 intermediates
            int m = tid >> 2, wq = (tid & 3) * 4;
            *(uint4*)&Ac[m * 20 + wq] = *(const uint4*)&g_hc[(size_t)(eBase + m) * 64 + kt * 16 + wq];
            *(uint4*)&Ag[m * 20 + wq] = *(const uint4*)&g_hg[(size_t)(eBase + m) * 64 + kt * 16 + wq];
        }
        {   // B fills
            const uint4* sc = (const uint4*)&g_w2ct[kt * 2048];
            const uint4* sg = (const uint4*)&g_w2gt[kt * 2048];
#pragma unroll
            for (int l = 0; l < 2; l++) {
                int i4 = tid + l * 256;
                int n = i4 >> 2, wq = (i4 & 3) * 4;
                *(uint4*)&Bc[n * 20 + wq] = sc[i4];
                *(uint4*)&Bg[n * 20 + wq] = sg[i4];
            }
        }
        __syncthreads();
#pragma unroll
        for (int k16 = 0; k16 < 2; k16++) {
            unsigned ac[2][4], ag[2][4], bc[4][2], bg[4][2];
#pragma unroll
            for (int mi = 0; mi < 2; mi++) {
                ldsm4(ac[mi], aBaseC + (mi * 16 * 20 + k16 * 8) * 4);
                ldsm4(ag[mi], aBaseG + (mi * 16 * 20 + k16 * 8) * 4);
            }
#pragma unroll
            for (int ni = 0; ni < 4; ni++) {
                ldsm2(bc[ni], bBaseC + (ni * 8 * 20 + k16 * 8) * 4);
                ldsm2(bg[ni], bBaseG + (ni * 8 * 20 + k16 * 8) * 4);
            }
#pragma unroll
            for (int mi = 0; mi < 2; mi++)
#pragma unroll
                for (int ni = 0; ni < 4; ni++) {
                    mma16(accc[mi][ni], ac[mi], bc[ni]);
                    mma16(accg[mi][ni], ag[mi], bg[ni]);
                }
        }
        __syncthreads();
    }

    // ---- LN partials ----
#pragma unroll
    for (int mi = 0; mi < 2; mi++)
#pragma unroll
        for (int h = 0; h < 2; h++) {
            int rloc = wm * 32 + mi * 16 + grp + 8 * h;
            float sc = 0.f, sc2 = 0.f, sg = 0.f, sg2 = 0.f;
#pragma unroll
            for (int ni = 0; ni < 4; ni++) {
                float c0 = accc[mi][ni][2 * h], c1 = accc[mi][ni][2 * h + 1];
                float g0 = accg[mi][ni][2 * h], g1 = accg[mi][ni][2 * h + 1];
                sc += c0 + c1; sc2 += c0 * c0 + c1 * c1;
                sg += g0 + g1; sg2 += g0 * g0 + g1 * g1;
            }
#pragma unroll
            for (int off = 1; off < 4; off <<= 1) {
                sc  += __shfl_xor_sync(0xffffffffu, sc,  off, 4);
                sc2 += __shfl_xor_sync(0xffffffffu, sc2, off, 4);
                sg  += __shfl_xor_sync(0xffffffffu, sg,  off, 4);
                sg2 += __shfl_xor_sync(0xffffffffu, sg2, off, 4);
            }
            if (qid == 0) red[rloc][wn] = make_float4(sc, sc2, sg, sg2);
        }
    __syncthreads();

#pragma unroll
    for (int mi = 0; mi < 2; mi++)
#pragma unroll
        for (int h = 0; h < 2; h++) {
            int rloc = wm * 32 + mi * 16 + grp + 8 * h;
            float4 p0 = red[rloc][0], p1 = red[rloc][1], p2 = red[rloc][2], p3 = red[rloc][3];
            float sc = p0.x + p1.x + p2.x + p3.x;
            float sc2 = p0.y + p1.y + p2.y + p3.y;
            float sg = p0.z + p1.z + p2.z + p3.z;
            float sg2 = p0.w + p1.w + p2.w + p3.w;
            float mc = sc * (1.f / 128.f);
            float vc = fmaxf(sc2 * (1.f / 128.f) - mc * mc, 0.f);
            float rc = rsqrtf(vc + 1e-5f);
            float mg = sg * (1.f / 128.f);
            float vg = fmaxf(sg2 * (1.f / 128.f) - mg * mg, 0.f);
            float rg = rsqrtf(vg + 1e-5f);

            size_t e = eBase + rloc;
            float s0 = sw7[rloc][0], s1 = sw7[rloc][1], s2 = sw7[rloc][2], s3 = sw7[rloc][3];
            float s4 = sw7[rloc][4], s5 = sw7[rloc][5], s6 = sw7[rloc][6];
            float* ap = g_nodeagg + ((size_t)idxT[rloc] << 7);
#pragma unroll
            for (int ni = 0; ni < 4; ni++) {
                int c = wn * 32 + ni * 8 + qid * 2;
                float hc0 = (accc[mi][ni][2 * h] - mc) * rc * __ldg(&lncg[c]) + __ldg(&lncb[c]);
                float hg0 = (accg[mi][ni][2 * h] - mg) * rg * __ldg(&lngg[c]) + __ldg(&lngb[c]);
                float nl0 = siluf_(hc0) * sigmoidf_(hg0);
                float hc1 = (accc[mi][ni][2 * h + 1] - mc) * rc * __ldg(&lncg[c + 1]) + __ldg(&lncb[c + 1]);
                float hg1 = (accg[mi][ni][2 * h + 1] - mg) * rg * __ldg(&lngg[c + 1]) + __ldg(&lngb[c + 1]);
                float nl1 = siluf_(hc1) * sigmoidf_(hg1);
                g_nl[e * 64 + (c >> 1)] = pack2(nl0, nl1);
                float sw0 = s0 * Wenv_s[0][c] + s1 * Wenv_s[1][c] + s2 * Wenv_s[2][c]
                          + s3 * Wenv_s[3][c] + s4 * Wenv_s[4][c] + s5 * Wenv_s[5][c]
                          + s6 * Wenv_s[6][c];
                float sw1 = s0 * Wenv_s[0][c + 1] + s1 * Wenv_s[1][c + 1] + s2 * Wenv_s[2][c + 1]
                          + s3 * Wenv_s[3][c + 1] + s4 * Wenv_s[4][c + 1] + s5 * Wenv_s[5][c + 1]
                          + s6 * Wenv_s[6][c + 1];
                atomicAdd(ap + c, nl0 * sw0);
                atomicAdd(ap + c + 1, nl1 * sw1);
            }
        }
}

// ============ kernel 3: delta_edge_dir = silu(nl@We1)@We2 -> atomic esum/cnt
// block M=64, two-stage f16 GEMM; warps 2m x 4n, warptile 32x32.
__global__ __launch_bounds__(256) void k_edge_ffn(const int* __restrict__ d2u)
{
    __shared__ __align__(16) unsigned As[64 * 20];
    __shared__ __align__(16) unsigned Bs[128 * 20];
    __shared__ __align__(16) unsigned t1[64 * 68];   // [m][kpair] pitch 68, K=128
    __shared__ int idxU[64];

    const int tid = threadIdx.x;
    const int eBase = blockIdx.x * 64;
    const int w = tid >> 5, lane = tid & 31;
    const int wm = w & 1, wn = w >> 1;
    const int grp = lane >> 2, qid = lane & 3;
    if (tid < 64) idxU[tid] = d2u[eBase + tid];

    const int aRow = wm * 32 + (lane & 7) + ((lane >> 3) & 1) * 8;
    const int aCol = ((lane >> 4) & 1) * 4;
    const unsigned aBase = sptr(As) + (aRow * 20 + aCol) * 4;
    const unsigned tBase = sptr(t1) + (aRow * 68 + aCol) * 4;
    const unsigned bBase = sptr(Bs) + ((wn * 32 + (lane & 7)) * 20 + ((lane >> 3) & 1) * 4) * 4;

    float acc[2][4][4];
#pragma unroll
    for (int mi = 0; mi < 2; mi++)
#pragma unroll
        for (int ni = 0; ni < 4; ni++)
#pragma unroll
            for (int q = 0; q < 4; q++) acc[mi][ni][q] = 0.f;

    __syncthreads();

    // stage 1: silu(nl @ We1)
    for (int kt = 0; kt < 4; kt++) {
        {
            int m = tid >> 2, wq = (tid & 3) * 4;
            *(uint4*)&As[m * 20 + wq] = *(const uint4*)&g_nl[(size_t)(eBase + m) * 64 + kt * 16 + wq];
        }
        {
            const uint4* src = (const uint4*)&g_we1t[kt * 2048];
#pragma unroll
            for (int l = 0; l < 2; l++) {
                int i4 = tid + l * 256;
                int n = i4 >> 2, wq = (i4 & 3) * 4;
                *(uint4*)&Bs[n * 20 + wq] = src[i4];
            }
        }
        __syncthreads();
#pragma unroll
        for (int k16 = 0; k16 < 2; k16++) {
            unsigned a[2][4], b[4][2];
#pragma unroll
            for (int mi = 0; mi < 2; mi++) ldsm4(a[mi], aBase + (mi * 16 * 20 + k16 * 8) * 4);
#pragma unroll
            for (int ni = 0; ni < 4; ni++) ldsm2(b[ni], bBase + (ni * 8 * 20 + k16 * 8) * 4);
#pragma unroll
            for (int mi = 0; mi < 2; mi++)
#pragma unroll
                for (int ni = 0; ni < 4; ni++) mma16(acc[mi][ni], a[mi], b[ni]);
        }
        __syncthreads();
    }
    // silu -> t1 (half2, [m][kpair] pitch 68)
#pragma unroll
    for (int mi = 0; mi < 2; mi++)
#pragma unroll
        for (int h = 0; h < 2; h++) {
            int r = wm * 32 + mi * 16 + grp + 8 * h;
#pragma unroll
            for (int ni = 0; ni < 4; ni++) {
                int c = wn * 32 + ni * 8 + qid * 2;
                t1[r * 68 + (c >> 1)] = pack2(siluf_(acc[mi][ni][2 * h]), siluf_(acc[mi][ni][2 * h + 1]));
            }
        }
    __syncthreads();

    // stage 2: t1 @ We2
    float acc2[2][4][4];
#pragma unroll
    for (int mi = 0; mi < 2; mi++)
#pragma unroll
        for (int ni = 0; ni < 4; ni++)
#pragma unroll
            for (int q = 0; q < 4; q++) acc2[mi][ni][q] = 0.f;

    for (int kt = 0; kt < 4; kt++) {
        {
            const uint4* src = (const uint4*)&g_we2t[kt * 2048];
#pragma unroll
            for (int l = 0; l < 2; l++) {
                int i4 = tid + l * 256;
                int n = i4 >> 2, wq = (i4 & 3) * 4;
                *(uint4*)&Bs[n * 20 + wq] = src[i4];
            }
        }
        __syncthreads();
#pragma unroll
        for (int k16 = 0; k16 < 2; k16++) {
            unsigned a[2][4], b[4][2];
#pragma unroll
            for (int mi = 0; mi < 2; mi++)
                ldsm4(a[mi], tBase + (mi * 16 * 68 + kt * 16 + k16 * 8) * 4);
#pragma unroll
            for (int ni = 0; ni < 4; ni++) ldsm2(b[ni], bBase + (ni * 8 * 20 + k16 * 8) * 4);
#pragma unroll
            for (int mi = 0; mi < 2; mi++)
#pragma unroll
                for (int ni = 0; ni < 4; ni++) mma16(acc2[mi][ni], a[mi], b[ni]);
        }
        __syncthreads();
    }

#pragma unroll
    for (int mi = 0; mi < 2; mi++)
#pragma unroll
        for (int h = 0; h < 2; h++) {
            int rloc = wm * 32 + mi * 16 + grp + 8 * h;
            int u = idxU[rloc];
            float* ep = g_esum + ((size_t)u << 7);
#pragma unroll
            for (int ni = 0; ni < 4; ni++) {
                int c = wn * 32 + ni * 8 + qid * 2;
                atomicAdd(ep + c,     acc2[mi][ni][2 * h]);
                atomicAdd(ep + c + 1, acc2[mi][ni][2 * h + 1]);
            }
            if (wn == 0 && qid == 0) atomicAdd(&g_cnt[u], 1.0f);
        }
}

// ============ kernel 4: delta_node = silu(agg@Wn1)@Wn2 + res -> out_node
__global__ __launch_bounds__(256) void k_node_ffn(
    const float* __restrict__ node_feat, const float* __restrict__ node_res_w,
    float* __restrict__ out_node)
{
    __shared__ __align__(16) unsigned As[64 * 20];
    __shared__ __align__(16) unsigned Bs[128 * 20];
    __shared__ __align__(16) unsigned t1[64 * 68];

    const int tid = threadIdx.x;
    const int nBase = blockIdx.x * 64;
    const int w = tid >> 5, lane = tid & 31;
    const int wm = w & 1, wn = w >> 1;
    const int grp = lane >> 2, qid = lane & 3;

    const int aRow = wm * 32 + (lane & 7) + ((lane >> 3) & 1) * 8;
    const int aCol = ((lane >> 4) & 1) * 4;
    const unsigned aBase = sptr(As) + (aRow * 20 + aCol) * 4;
    const unsigned tBase = sptr(t1) + (aRow * 68 + aCol) * 4;
    const unsigned bBase = sptr(Bs) + ((wn * 32 + (lane & 7)) * 20 + ((lane >> 3) & 1) * 4) * 4;

    float acc[2][4][4];
#pragma unroll
    for (int mi = 0; mi < 2; mi++)
#pragma unroll
        for (int ni = 0; ni < 4; ni++)
#pragma unroll
            for (int q = 0; q < 4; q++) acc[mi][ni][q] = 0.f;

    for (int kt = 0; kt < 4; kt++) {
        {
            int m = tid >> 2, k8 = (tid & 3) * 8;
            int row = nBase + m;
            uint4 q4 = make_uint4(0u, 0u, 0u, 0u);
            if (row < NN) {
                const float* p = g_nodeagg + ((size_t)row << 7) + kt * 32 + k8;
                float4 v0 = *(const float4*)p;
                float4 v1 = *(const float4*)(p + 4);
                q4 = make_uint4(pack2(v0.x, v0.y), pack2(v0.z, v0.w),
                                pack2(v1.x, v1.y), pack2(v1.z, v1.w));
            }
            *(uint4*)&As[(tid >> 2) * 20 + (k8 >> 1)] = q4;
        }
        {
            const uint4* src = (const uint4*)&g_wn1t[kt * 2048];
#pragma unroll
            for (int l = 0; l < 2; l++) {
                int i4 = tid + l * 256;
                int n = i4 >> 2, wq = (i4 & 3) * 4;
                *(uint4*)&Bs[n * 20 + wq] = src[i4];
            }
        }
        __syncthreads();
#pragma unroll
        for (int k16 = 0; k16 < 2; k16++) {
            unsigned a[2][4], b[4][2];
#pragma unroll
            for (int mi = 0; mi < 2; mi++) ldsm4(a[mi], aBase + (mi * 16 * 20 + k16 * 8) * 4);
#pragma unroll
            for (int ni = 0; ni < 4; ni++) ldsm2(b[ni], bBase + (ni * 8 * 20 + k16 * 8) * 4);
#pragma unroll
            for (int mi = 0; mi < 2; mi++)
#pragma unroll
                for (int ni = 0; ni < 4; ni++) mma16(acc[mi][ni], a[mi], b[ni]);
        }
        __syncthreads();
    }
#pragma unroll
    for (int mi = 0; mi < 2; mi++)
#pragma unroll
        for (int h = 0; h < 2; h++) {
            int r = wm * 32 + mi * 16 + grp + 8 * h;
#pragma unroll
            for (int ni = 0; ni < 4; ni++) {
                int c = wn * 32 + ni * 8 + qid * 2;
                t1[r * 68 + (c >> 1)] = pack2(siluf_(acc[mi][ni][2 * h]), siluf_(acc[mi][ni][2 * h + 1]));
            }
        }
    __syncthreads();

    float acc2[2][4][4];
#pragma unroll
    for (int mi = 0; mi < 2; mi++)
#pragma unroll
        for (int ni = 0; ni < 4; ni++)
#pragma unroll
            for (int q = 0; q < 4; q++) acc2[mi][ni][q] = 0.f;

    for (int kt = 0; kt < 4; kt++) {
        {
            const uint4* src = (const uint4*)&g_wn2t[kt * 2048];
#pragma unroll
            for (int l = 0; l < 2; l++) {
                int i4 = tid + l * 256;
                int n = i4 >> 2, wq = (i4 & 3) * 4;
                *(uint4*)&Bs[n * 20 + wq] = src[i4];
            }
        }
        __syncthreads();
#pragma unroll
        for (int k16 = 0; k16 < 2; k16++) {
            unsigned a[2][4], b[4][2];
#pragma unroll
            for (int mi = 0; mi < 2; mi++)
                ldsm4(a[mi], tBase + (mi * 16 * 68 + kt * 16 + k16 * 8) * 4);
#pragma unroll
            for (int ni = 0; ni < 4; ni++) ldsm2(b[ni], bBase + (ni * 8 * 20 + k16 * 8) * 4);
#pragma unroll
            for (int mi = 0; mi < 2; mi++)
#pragma unroll
                for (int ni = 0; ni < 4; ni++) mma16(acc2[mi][ni], a[mi], b[ni]);
        }
        __syncthreads();
    }

#pragma unroll
    for (int mi = 0; mi < 2; mi++)
#pragma unroll
        for (int h = 0; h < 2; h++) {
            int row = nBase + wm * 32 + mi * 16 + grp + 8 * h;
            if (row >= NN) continue;
            const float* nf = node_feat + ((size_t)row << 7);
            float* op = out_node + ((size_t)row << 7);
#pragma unroll
            for (int ni = 0; ni < 4; ni++) {
                int c = wn * 32 + ni * 8 + qid * 2;
                float o0 = acc2[mi][ni][2 * h]     + __ldg(&node_res_w[c])     * nf[c];
                float o1 = acc2[mi][ni][2 * h + 1] + __ldg(&node_res_w[c + 1]) * nf[c + 1];
                *(float2*)(op + c) = make_float2(o0, o1);
            }
        }
}

// ============ kernel 5: edge output = esum/max(cnt,1) + res*edge_feat
__global__ void k_edge_final(const float* __restrict__ edge_feat,
                             const float* __restrict__ edge_res_w,
                             float* __restrict__ out_edge)
{
    size_t i = (size_t)blockIdx.x * blockDim.x + threadIdx.x;
    const size_t total = (size_t)EUN * 128 / 4;
    if (i >= total) return;
    size_t u = (i * 4) >> 7;
    int c = (int)((i * 4) & 127);
    float inv = __fdividef(1.0f, fmaxf(g_cnt[u], 1.0f));
    float4 es = ((const float4*)g_esum)[i];
    float4 ef = ((const float4*)edge_feat)[i];
    float4 rw = *(const float4*)&edge_res_w[c];
    float4 o;
    o.x = es.x * inv + rw.x * ef.x;
    o.y = es.y * inv + rw.y * ef.y;
    o.z = es.z * inv + rw.z * ef.z;
    o.w = es.w * inv + rw.w * ef.w;
    ((float4*)out_edge)[i] = o;
}

// ---------------- launch ----------------
extern "C" void kernel_launch(void* const* d_in, const int* in_sizes, int n_in,
                              void* d_out, int out_size)
{
    (void)in_sizes; (void)n_in; (void)out_size;
    const float* node_feat     = (const float*)d_in[0];
    const float* edge_feat     = (const float*)d_in[1];
    const float* smooth_weight = (const float*)d_in[2];
    const int*   source_index  = (const int*)d_in[3];
    const int*   target_index  = (const int*)d_in[4];
    const int*   d2u           = (const int*)d_in[5];
    const float* W_env         = (const float*)d_in[6];
    const float* Wc1           = (const float*)d_in[7];
    const float* Wc2           = (const float*)d_in[8];
    const float* Wg1           = (const float*)d_in[9];
    const float* Wg2           = (const float*)d_in[10];
    const float* ln_c_g        = (const float*)d_in[11];
    const float* ln_c_b        = (const float*)d_in[12];
    const float* ln_g_g        = (const float*)d_in[13];
    const float* ln_g_b        = (const float*)d_in[14];
    const float* Wn1           = (const float*)d_in[15];
    const float* Wn2           = (const float*)d_in[16];
    const float* We1           = (const float*)d_in[17];
    const float* We2           = (const float*)d_in[18];
    const float* node_res_w    = (const float*)d_in[19];
    const float* edge_res_w    = (const float*)d_in[20];

    float* out_node = (float*)d_out;
    float* out_edge = out_node + (size_t)NN * 128;

    k_prep<<<(12 * 256 * 16 + 6 * 8192 + 255) / 256, 256>>>(Wc1, Wg1, Wc2, Wg2, We1, We2, Wn1, Wn2);
    k_zero<<<592, 256>>>();

    k_gemm1<<<EDN / 64, 256>>>(node_feat, edge_feat, source_index, target_index, d2u);

    k_gemm2_ln<<<EDN / 64, 256>>>(ln_c_g, ln_c_b, ln_g_g, ln_g_b,
                                  smooth_weight, W_env, d2u, target_index);

    k_edge_ffn<<<EDN / 64, 256>>>(d2u);

    k_node_ffn<<<(NN + 63) / 64, 256>>>(node_feat, node_res_w, out_node);

    k_edge_final<<<(EUN * 128 / 4 + 255) / 256, 256>>>(edge_feat, edge_res_w, out_edge);
}